// round 2
// baseline (speedup 1.0000x reference)
#include <cuda_runtime.h>
#include <math.h>

#define NNODE 4096
#define DIM   256
#define TOPK  16
#define NEDGE 17   // 16 top-k + self loop

// ---------------- static scratch (no allocations allowed) ----------------
__device__ float g_h   [NNODE * DIM];          // graph-learn hidden
__device__ float g_x   [NNODE * DIM];          // running node features
__device__ float g_hf  [NNODE * DIM];          // GAT projected features
__device__ float g_qkv [NNODE * 768];
__device__ float g_attn[NNODE * DIM];
__device__ float g_tmp [NNODE * DIM];
__device__ float g_ff  [NNODE * 512];
__device__ float g_ssrc[NNODE * 4];
__device__ float g_sdst[NNODE * 4];
__device__ int   g_nbr [NNODE * NEDGE];

// ---------------- generic tiled SGEMM ----------------
// C[M,N](ldc) = act(alpha * A@B + bias); A[M,K](lda) row-major.
// TRANSB=0: B[K,N](ldb). TRANSB=1: B[N,K](ldb). Batched via blockIdx.z.
// ACT: 0=none, 1=relu, 2=tanh.  Requires M%64==0, N%64==0, K%16==0.
template<int TRANSB, int ACT>
__global__ void __launch_bounds__(256)
sgemm(const float* __restrict__ A, const float* __restrict__ B,
      float* __restrict__ C, const float* __restrict__ bias,
      int M, int N, int K, int lda, int ldb, int ldc, float alpha)
{
    __shared__ float As[16][65];
    __shared__ float Bs[16][65];

    const int t  = threadIdx.x;
    const int tx = t & 15;
    const int ty = t >> 4;
    const int row0 = blockIdx.y * 64;
    const int col0 = blockIdx.x * 64;

    float acc[4][4];
#pragma unroll
    for (int i = 0; i < 4; i++)
#pragma unroll
        for (int j = 0; j < 4; j++) acc[i][j] = 0.f;

    for (int k0 = 0; k0 < K; k0 += 16) {
#pragma unroll
        for (int i = 0; i < 4; i++) {
            int idx = t + i * 256;
            int r = idx >> 4, c = idx & 15;
            As[c][r] = A[(long long)(row0 + r) * lda + (k0 + c)];
        }
        if (!TRANSB) {
#pragma unroll
            for (int i = 0; i < 4; i++) {
                int idx = t + i * 256;
                int r = idx >> 6, c = idx & 63;
                Bs[r][c] = B[(long long)(k0 + r) * ldb + (col0 + c)];
            }
        } else {
#pragma unroll
            for (int i = 0; i < 4; i++) {
                int idx = t + i * 256;
                int nn = idx >> 4, kk = idx & 15;
                Bs[kk][nn] = B[(long long)(col0 + nn) * ldb + (k0 + kk)];
            }
        }
        __syncthreads();
#pragma unroll
        for (int k = 0; k < 16; k++) {
            float a0 = As[k][ty * 4 + 0], a1 = As[k][ty * 4 + 1];
            float a2 = As[k][ty * 4 + 2], a3 = As[k][ty * 4 + 3];
            float b0 = Bs[k][tx * 4 + 0], b1 = Bs[k][tx * 4 + 1];
            float b2 = Bs[k][tx * 4 + 2], b3 = Bs[k][tx * 4 + 3];
            acc[0][0] += a0 * b0; acc[0][1] += a0 * b1; acc[0][2] += a0 * b2; acc[0][3] += a0 * b3;
            acc[1][0] += a1 * b0; acc[1][1] += a1 * b1; acc[1][2] += a1 * b2; acc[1][3] += a1 * b3;
            acc[2][0] += a2 * b0; acc[2][1] += a2 * b1; acc[2][2] += a2 * b2; acc[2][3] += a2 * b3;
            acc[3][0] += a3 * b0; acc[3][1] += a3 * b1; acc[3][2] += a3 * b2; acc[3][3] += a3 * b3;
        }
        __syncthreads();
    }
#pragma unroll
    for (int i = 0; i < 4; i++) {
        int r = row0 + ty * 4 + i;
#pragma unroll
        for (int j = 0; j < 4; j++) {
            int c = col0 + tx * 4 + j;
            float v = alpha * acc[i][j];
            if (bias) v += bias[c];
            if (ACT == 1) v = fmaxf(v, 0.f);
            else if (ACT == 2) v = tanhf(v);
            C[(long long)r * ldc + c] = v;
        }
    }
}

// ---------------- fused flash attention ----------------
// Grid: (query_tile 0..63, head 0..3). 64 queries per block, dh=64, 4 heads.
// qkv row layout: [q(256) | k(256) | v(256)], head h at col h*64 within each.
// Online softmax; Q pre-scaled by 1/8. Output written to out[n, h*64+c].
#define FA_SMEM_FLOATS (4 * 64 * 65 + 3 * 64)
__global__ void __launch_bounds__(256)
flash_attn(const float* __restrict__ qkv, float* __restrict__ out)
{
    extern __shared__ float sm[];
    float* Qs   = sm;                 // [64][65]
    float* Ks   = Qs + 64 * 65;       // [64][65]
    float* Vs   = Ks + 64 * 65;       // [64][65]
    float* Ps   = Vs + 64 * 65;       // [64][65]
    float* m_s  = Ps + 64 * 65;       // [64]
    float* l_s  = m_s + 64;           // [64]
    float* sc_s = l_s + 64;           // [64]

    const int h  = blockIdx.y;
    const int q0 = blockIdx.x * 64;
    const int t  = threadIdx.x;
    const int tx = t & 15;
    const int ty = t >> 4;

    for (int i = t; i < 64 * 64; i += 256) {
        int r = i >> 6, c = i & 63;
        Qs[r * 65 + c] = qkv[(size_t)(q0 + r) * 768 + h * 64 + c] * 0.125f;
    }
    if (t < 64) { m_s[t] = -1e30f; l_s[t] = 0.f; }

    float o[4][4] = {};

    for (int k0 = 0; k0 < NNODE; k0 += 64) {
        __syncthreads();
        for (int i = t; i < 64 * 64; i += 256) {
            int r = i >> 6, c = i & 63;
            Ks[r * 65 + c] = qkv[(size_t)(k0 + r) * 768 + 256 + h * 64 + c];
            Vs[r * 65 + c] = qkv[(size_t)(k0 + r) * 768 + 512 + h * 64 + c];
        }
        __syncthreads();

        // S = Q @ K^T  (each thread: 4 rows x 4 key-cols)
        float s[4][4] = {};
#pragma unroll
        for (int d = 0; d < 64; d++) {
            float a0 = Qs[(ty * 4 + 0) * 65 + d], a1 = Qs[(ty * 4 + 1) * 65 + d];
            float a2 = Qs[(ty * 4 + 2) * 65 + d], a3 = Qs[(ty * 4 + 3) * 65 + d];
            float b0 = Ks[(tx * 4 + 0) * 65 + d], b1 = Ks[(tx * 4 + 1) * 65 + d];
            float b2 = Ks[(tx * 4 + 2) * 65 + d], b3 = Ks[(tx * 4 + 3) * 65 + d];
            s[0][0] += a0 * b0; s[0][1] += a0 * b1; s[0][2] += a0 * b2; s[0][3] += a0 * b3;
            s[1][0] += a1 * b0; s[1][1] += a1 * b1; s[1][2] += a1 * b2; s[1][3] += a1 * b3;
            s[2][0] += a2 * b0; s[2][1] += a2 * b1; s[2][2] += a2 * b2; s[2][3] += a2 * b3;
            s[3][0] += a3 * b0; s[3][1] += a3 * b1; s[3][2] += a3 * b2; s[3][3] += a3 * b3;
        }
#pragma unroll
        for (int i = 0; i < 4; i++)
#pragma unroll
            for (int j = 0; j < 4; j++)
                Ps[(ty * 4 + i) * 65 + tx * 4 + j] = s[i][j];
        __syncthreads();

        // online softmax update, one thread per query row
        if (t < 64) {
            float m_old = m_s[t];
            float mt = m_old;
            for (int c = 0; c < 64; c++) mt = fmaxf(mt, Ps[t * 65 + c]);
            float sc = __expf(m_old - mt);
            float l = l_s[t] * sc;
            for (int c = 0; c < 64; c++) {
                float p = __expf(Ps[t * 65 + c] - mt);
                Ps[t * 65 + c] = p;
                l += p;
            }
            m_s[t] = mt; l_s[t] = l; sc_s[t] = sc;
        }
        __syncthreads();

        // rescale accumulators, then O += P @ V
#pragma unroll
        for (int i = 0; i < 4; i++) {
            float sc = sc_s[ty * 4 + i];
#pragma unroll
            for (int j = 0; j < 4; j++) o[i][j] *= sc;
        }
#pragma unroll
        for (int k = 0; k < 64; k++) {
            float p0 = Ps[(ty * 4 + 0) * 65 + k], p1 = Ps[(ty * 4 + 1) * 65 + k];
            float p2 = Ps[(ty * 4 + 2) * 65 + k], p3 = Ps[(ty * 4 + 3) * 65 + k];
            float v0 = Vs[k * 65 + tx * 4 + 0], v1 = Vs[k * 65 + tx * 4 + 1];
            float v2 = Vs[k * 65 + tx * 4 + 2], v3 = Vs[k * 65 + tx * 4 + 3];
            o[0][0] += p0 * v0; o[0][1] += p0 * v1; o[0][2] += p0 * v2; o[0][3] += p0 * v3;
            o[1][0] += p1 * v0; o[1][1] += p1 * v1; o[1][2] += p1 * v2; o[1][3] += p1 * v3;
            o[2][0] += p2 * v0; o[2][1] += p2 * v1; o[2][2] += p2 * v2; o[2][3] += p2 * v3;
            o[3][0] += p3 * v0; o[3][1] += p3 * v1; o[3][2] += p3 * v2; o[3][3] += p3 * v3;
        }
    }
    __syncthreads();

#pragma unroll
    for (int i = 0; i < 4; i++) {
        float inv = 1.f / l_s[ty * 4 + i];
#pragma unroll
        for (int j = 0; j < 4; j++)
            out[(size_t)(q0 + ty * 4 + i) * DIM + h * 64 + tx * 4 + j] = o[i][j] * inv;
    }
}

// ---------------- top-k neighbor selection ----------------
// One block per row: sim row = relu(h[row]·h[j]) with self masked, then 16
// iterative argmax passes (lowest-index tie-break, matching jax.lax.top_k).
__global__ void __launch_bounds__(256)
topk_kernel(const float* __restrict__ h, int* __restrict__ nbr)
{
    const int row = blockIdx.x, t = threadIdx.x;
    __shared__ float4 qh[64];
    __shared__ float  sim[NNODE];
    __shared__ float  rv[256];
    __shared__ int    ri[256];

    if (t < 64) qh[t] = ((const float4*)(h + (size_t)row * DIM))[t];
    __syncthreads();

    const float4* hv = (const float4*)h;
    for (int j = t; j < NNODE; j += 256) {
        const float4* r = hv + (size_t)j * 64;
        float d = 0.f;
#pragma unroll 16
        for (int k = 0; k < 64; k++) {
            float4 a = qh[k], b = r[k];
            d += a.x * b.x + a.y * b.y + a.z * b.z + a.w * b.w;
        }
        float v = fmaxf(d, 0.f);
        if (j == row) v = -1e9f;
        sim[j] = v;
    }
    __syncthreads();

    for (int it = 0; it < TOPK; it++) {
        float bv = -1e30f; int bi = NNODE;
        for (int j = t; j < NNODE; j += 256) {
            float v = sim[j];
            if (v > bv || (v == bv && j < bi)) { bv = v; bi = j; }
        }
        rv[t] = bv; ri[t] = bi;
        __syncthreads();
        for (int off = 128; off >= 1; off >>= 1) {
            if (t < off) {
                float v2 = rv[t + off]; int i2 = ri[t + off];
                if (v2 > rv[t] || (v2 == rv[t] && i2 < ri[t])) { rv[t] = v2; ri[t] = i2; }
            }
            __syncthreads();
        }
        if (t == 0) { nbr[row * NEDGE + it] = ri[0]; sim[ri[0]] = -2e9f; }
        __syncthreads();
    }
    if (t == 0) nbr[row * NEDGE + TOPK] = row;
}

// ---------------- GAT per-node attention scores ----------------
__global__ void __launch_bounds__(256)
gat_score(const float* __restrict__ hf, const float* __restrict__ asrc,
          const float* __restrict__ adst, float* __restrict__ ssrc,
          float* __restrict__ sdst, int heads)
{
    const int n = blockIdx.x, t = threadIdx.x;
    const int F = DIM / heads;
    __shared__ float rs[256], rd[256];
    float v = hf[(size_t)n * DIM + t];
    rs[t] = v * asrc[t];
    rd[t] = v * adst[t];
    __syncthreads();
    for (int off = F >> 1; off >= 1; off >>= 1) {
        if ((t & (F - 1)) < off) { rs[t] += rs[t + off]; rd[t] += rd[t + off]; }
        __syncthreads();
    }
    if ((t & (F - 1)) == 0) {
        int hh = t / F;
        ssrc[n * heads + hh] = rs[t];
        sdst[n * heads + hh] = rd[t];
    }
}

// ---------------- GAT aggregation (17 fixed edges per dst) ----------------
__global__ void __launch_bounds__(256)
gat_agg(const float* __restrict__ hf, const int* __restrict__ nbr,
        const float* __restrict__ ssrc, const float* __restrict__ sdst,
        const float* __restrict__ bias, float* __restrict__ out,
        int heads, int relu, int transout)
{
    const int n = blockIdx.x, t = threadIdx.x;
    const int F = DIM / heads;
    const int hh = t / F, f = t - hh * F;
    __shared__ int   nb[NEDGE];
    __shared__ float al[4 * NEDGE];

    if (t < NEDGE) nb[t] = nbr[n * NEDGE + t];
    __syncthreads();
    if (f < NEDGE) {
        float e = ssrc[nb[f] * heads + hh] + sdst[n * heads + hh];
        e = (e > 0.f) ? e : 0.2f * e;   // leaky_relu(0.2)
        al[hh * NEDGE + f] = e;
    }
    __syncthreads();
    if (f == 0) {
        float m = -1e30f;
        for (int j = 0; j < NEDGE; j++) m = fmaxf(m, al[hh * NEDGE + j]);
        float s = 0.f;
        for (int j = 0; j < NEDGE; j++) { float p = expf(al[hh * NEDGE + j] - m); al[hh * NEDGE + j] = p; s += p; }
        float inv = 1.f / s;
        for (int j = 0; j < NEDGE; j++) al[hh * NEDGE + j] *= inv;
    }
    __syncthreads();
    float acc = 0.f;
#pragma unroll
    for (int j = 0; j < NEDGE; j++)
        acc += al[hh * NEDGE + j] * hf[(size_t)nb[j] * DIM + t];
    float v = acc + bias[t];
    if (relu) v = fmaxf(v, 0.f);
    if (transout) out[(size_t)t * NNODE + n] = v;
    else          out[(size_t)n * DIM + t] = v;
}

// ---------------- layernorm (in place, 256-dim rows) ----------------
__global__ void __launch_bounds__(256)
ln_kernel(float* __restrict__ x, const float* __restrict__ g, const float* __restrict__ b)
{
    const int n = blockIdx.x, t = threadIdx.x;
    __shared__ float red[256];
    float v = x[(size_t)n * DIM + t];
    red[t] = v; __syncthreads();
    for (int off = 128; off >= 1; off >>= 1) { if (t < off) red[t] += red[t + off]; __syncthreads(); }
    float mu = red[0] * (1.f / 256.f); __syncthreads();
    float d = v - mu;
    red[t] = d * d; __syncthreads();
    for (int off = 128; off >= 1; off >>= 1) { if (t < off) red[t] += red[t + off]; __syncthreads(); }
    float var = red[0] * (1.f / 256.f);
    x[(size_t)n * DIM + t] = d * rsqrtf(var + 1e-5f) * g[t] + b[t];
}

__global__ void add_kernel(float* __restrict__ y, const float* __restrict__ x, int n)
{
    int i = blockIdx.x * blockDim.x + threadIdx.x;
    if (i < n) y[i] += x[i];
}

// ---------------- host orchestration ----------------
extern "C" void kernel_launch(void* const* d_in, const int* in_sizes, int n_in,
                              void* d_out, int out_size)
{
    const float* window   = (const float*)d_in[0];
    const float* gl_w     = (const float*)d_in[1];
    const float* gl_b     = (const float*)d_in[2];
    const float* enc_W    = (const float*)d_in[3];
    const float* enc_asrc = (const float*)d_in[4];
    const float* enc_adst = (const float*)d_in[5];
    const float* enc_b    = (const float*)d_in[6];
    const float* tr_wqkv  = (const float*)d_in[7];
    const float* tr_bqkv  = (const float*)d_in[8];
    const float* tr_wo    = (const float*)d_in[9];
    const float* tr_bo    = (const float*)d_in[10];
    const float* ln1g     = (const float*)d_in[11];
    const float* ln1b     = (const float*)d_in[12];
    const float* w1       = (const float*)d_in[13];
    const float* b1       = (const float*)d_in[14];
    const float* w2       = (const float*)d_in[15];
    const float* b2       = (const float*)d_in[16];
    const float* ln2g     = (const float*)d_in[17];
    const float* ln2b     = (const float*)d_in[18];
    const float* skw      = (const float*)d_in[19];
    const float* skb      = (const float*)d_in[20];
    const float* dec_W    = (const float*)d_in[21];
    const float* dec_asrc = (const float*)d_in[22];
    const float* dec_adst = (const float*)d_in[23];
    const float* dec_b    = (const float*)d_in[24];
    const float* dlW      = (const float*)d_in[25];
    const float* dlas     = (const float*)d_in[26];
    const float* dlad     = (const float*)d_in[27];
    const float* dlb      = (const float*)d_in[28];

    float *h, *x, *hf, *qkv, *attn, *tmp, *ff, *ssrc, *sdst;
    int* nbr;
    cudaGetSymbolAddress((void**)&h,    g_h);
    cudaGetSymbolAddress((void**)&x,    g_x);
    cudaGetSymbolAddress((void**)&hf,   g_hf);
    cudaGetSymbolAddress((void**)&qkv,  g_qkv);
    cudaGetSymbolAddress((void**)&attn, g_attn);
    cudaGetSymbolAddress((void**)&tmp,  g_tmp);
    cudaGetSymbolAddress((void**)&ff,   g_ff);
    cudaGetSymbolAddress((void**)&ssrc, g_ssrc);
    cudaGetSymbolAddress((void**)&sdst, g_sdst);
    cudaGetSymbolAddress((void**)&nbr,  g_nbr);

    cudaFuncSetAttribute(flash_attn, cudaFuncAttributeMaxDynamicSharedMemorySize,
                         FA_SMEM_FLOATS * (int)sizeof(float));

    // 1. graph learning: h = tanh(window @ gl_w + gl_b), then top-16 per row
    sgemm<0, 2><<<dim3(4, 64, 1), 256>>>(window, gl_w, h, gl_b,
                                         4096, 256, 256, 256, 256, 256, 1.f);
    topk_kernel<<<NNODE, 256>>>(h, nbr);

    // 2. encoder: 3 GAT layers (4 heads) with ReLU
    const float* xin = window;
    for (int i = 0; i < 3; i++) {
        sgemm<0, 0><<<dim3(4, 64, 1), 256>>>(xin, enc_W + (size_t)i * 65536, hf, nullptr,
                                             4096, 256, 256, 256, 256, 256, 1.f);
        gat_score<<<NNODE, 256>>>(hf, enc_asrc + i * 256, enc_adst + i * 256, ssrc, sdst, 4);
        gat_agg<<<NNODE, 256>>>(hf, nbr, ssrc, sdst, enc_b + i * 256, x, 4, 1, 0);
        xin = x;
    }

    // 3. transformer bottleneck ×2 (4 heads, dh=64)
    for (int l = 0; l < 2; l++) {
        sgemm<1, 0><<<dim3(12, 64, 1), 256>>>(x, tr_wqkv + (size_t)l * 768 * 256, qkv,
                                              tr_bqkv + l * 768,
                                              4096, 768, 256, 256, 256, 768, 1.f);
        flash_attn<<<dim3(64, 4), 256, FA_SMEM_FLOATS * sizeof(float)>>>(qkv, attn);
        sgemm<1, 0><<<dim3(4, 64, 1), 256>>>(attn, tr_wo + (size_t)l * 65536, tmp,
                                             tr_bo + l * 256,
                                             4096, 256, 256, 256, 256, 256, 1.f);
        add_kernel<<<NNODE, 256>>>(x, tmp, NNODE * DIM);
        ln_kernel<<<NNODE, 256>>>(x, ln1g + l * 256, ln1b + l * 256);
        sgemm<0, 1><<<dim3(8, 64, 1), 256>>>(x, w1 + (size_t)l * 131072, ff, b1 + l * 512,
                                             4096, 512, 256, 256, 512, 512, 1.f);
        sgemm<0, 0><<<dim3(4, 64, 1), 256>>>(ff, w2 + (size_t)l * 131072, tmp, b2 + l * 256,
                                             4096, 256, 512, 512, 256, 256, 1.f);
        add_kernel<<<NNODE, 256>>>(x, tmp, NNODE * DIM);
        ln_kernel<<<NNODE, 256>>>(x, ln2g + l * 256, ln2b + l * 256);
    }

    // 4. skip connection: x += window @ skip_w + skip_b
    sgemm<0, 0><<<dim3(4, 64, 1), 256>>>(window, skw, tmp, skb,
                                         4096, 256, 256, 256, 256, 256, 1.f);
    add_kernel<<<NNODE, 256>>>(x, tmp, NNODE * DIM);

    // 5. decoder: 2 GAT layers (4 heads) with ReLU
    for (int i = 0; i < 2; i++) {
        sgemm<0, 0><<<dim3(4, 64, 1), 256>>>(x, dec_W + (size_t)i * 65536, hf, nullptr,
                                             4096, 256, 256, 256, 256, 256, 1.f);
        gat_score<<<NNODE, 256>>>(hf, dec_asrc + i * 256, dec_adst + i * 256, ssrc, sdst, 4);
        gat_agg<<<NNODE, 256>>>(hf, nbr, ssrc, sdst, dec_b + i * 256, x, 4, 1, 0);
    }

    // 6. final single-head GAT, output transposed [256, 4096]
    sgemm<0, 0><<<dim3(4, 64, 1), 256>>>(x, dlW, hf, nullptr,
                                         4096, 256, 256, 256, 256, 256, 1.f);
    gat_score<<<NNODE, 256>>>(hf, dlas, dlad, ssrc, sdst, 1);
    gat_agg<<<NNODE, 256>>>(hf, nbr, ssrc, sdst, dlb, (float*)d_out, 1, 0, 1);
}

// round 3
// speedup vs baseline: 2.6428x; 2.6428x over previous
#include <cuda_runtime.h>
#include <math.h>

#define NNODE 4096
#define DIM   256
#define TOPK  16
#define NEDGE 17   // 16 top-k + self loop

// ---------------- static scratch (no allocations allowed) ----------------
__device__ float g_h   [NNODE * DIM];
__device__ float g_x   [NNODE * DIM];
__device__ float g_hf  [NNODE * DIM];
__device__ float g_qkv [NNODE * 768];
__device__ float g_attn[NNODE * DIM];
__device__ float g_tmp [NNODE * DIM];
__device__ float g_ff  [NNODE * 512];
__device__ float g_sim [(size_t)NNODE * NNODE];   // 64 MB similarity matrix
__device__ float g_ssrc[NNODE * 4];
__device__ float g_sdst[NNODE * 4];
__device__ int   g_nbr [NNODE * NEDGE];

// ================= 64x64-tile SGEMM (4x4 micro, K-tile 32) =================
// C[M,N] = act(alpha*A@B + bias) (+ R). ACT: 0 none, 1 relu, 2 tanh.
// Requires M%64==0, N%64==0, K%32==0, lda/ldb/ldc mult of 4.
template<int TRANSB, int ACT, int RESID>
__global__ void __launch_bounds__(256)
sgemm2(const float* __restrict__ A, const float* __restrict__ B,
       float* __restrict__ C, const float* __restrict__ bias,
       const float* __restrict__ R,
       int M, int N, int K, int lda, int ldb, int ldc, float alpha)
{
    __shared__ float As[32 * 68];   // [k][row]
    __shared__ float Bs[32 * 68];   // [k][col]
    const int t = threadIdx.x, tx = t & 15, ty = t >> 4;
    const int row0 = blockIdx.y * 64, col0 = blockIdx.x * 64;

    float acc[4][4] = {};

    for (int k0 = 0; k0 < K; k0 += 32) {
        {   // A: 64 rows x 32 k
            int row = t >> 2, kq = (t & 3) * 4;
#pragma unroll
            for (int g = 0; g < 2; g++) {
                int kk = kq + g * 16;
                float4 a = *(const float4*)&A[(size_t)(row0 + row) * lda + k0 + kk];
                As[(kk + 0) * 68 + row] = a.x; As[(kk + 1) * 68 + row] = a.y;
                As[(kk + 2) * 68 + row] = a.z; As[(kk + 3) * 68 + row] = a.w;
            }
        }
        if (!TRANSB) {
            int kk = t >> 4, c4 = (t & 15) * 4;
#pragma unroll
            for (int g = 0; g < 2; g++) {
                int k2 = kk + g * 16;
                float4 b = *(const float4*)&B[(size_t)(k0 + k2) * ldb + col0 + c4];
                *(float4*)&Bs[k2 * 68 + c4] = b;
            }
        } else {
            int n = t >> 2, kq = (t & 3) * 4;
#pragma unroll
            for (int g = 0; g < 2; g++) {
                int kk = kq + g * 16;
                float4 b = *(const float4*)&B[(size_t)(col0 + n) * ldb + k0 + kk];
                Bs[(kk + 0) * 68 + n] = b.x; Bs[(kk + 1) * 68 + n] = b.y;
                Bs[(kk + 2) * 68 + n] = b.z; Bs[(kk + 3) * 68 + n] = b.w;
            }
        }
        __syncthreads();
#pragma unroll
        for (int k = 0; k < 32; k++) {
            float4 a = *(const float4*)&As[k * 68 + ty * 4];
            float4 b = *(const float4*)&Bs[k * 68 + tx * 4];
            acc[0][0] += a.x * b.x; acc[0][1] += a.x * b.y; acc[0][2] += a.x * b.z; acc[0][3] += a.x * b.w;
            acc[1][0] += a.y * b.x; acc[1][1] += a.y * b.y; acc[1][2] += a.y * b.z; acc[1][3] += a.y * b.w;
            acc[2][0] += a.z * b.x; acc[2][1] += a.z * b.y; acc[2][2] += a.z * b.z; acc[2][3] += a.z * b.w;
            acc[3][0] += a.w * b.x; acc[3][1] += a.w * b.y; acc[3][2] += a.w * b.z; acc[3][3] += a.w * b.w;
        }
        __syncthreads();
    }
#pragma unroll
    for (int i = 0; i < 4; i++) {
        int r = row0 + ty * 4 + i;
#pragma unroll
        for (int j = 0; j < 4; j++) {
            int c = col0 + tx * 4 + j;
            float v = alpha * acc[i][j];
            if (bias) v += bias[c];
            if (ACT == 1) v = fmaxf(v, 0.f);
            else if (ACT == 2) v = tanhf(v);
            if (RESID) v += R[(size_t)r * ldc + c];
            C[(size_t)r * ldc + c] = v;
        }
    }
}

// ============ 128x128-tile SGEMM (8x8 micro, K-tile 16, FMA-bound) ============
// ACT==3: similarity mode (relu, diagonal = -1e9).
// Requires M%128==0, N%128==0, K%16==0.
template<int TRANSB, int ACT>
__global__ void __launch_bounds__(256)
sgemm_big(const float* __restrict__ A, const float* __restrict__ B,
          float* __restrict__ C, const float* __restrict__ bias,
          int M, int N, int K, int lda, int ldb, int ldc, float alpha)
{
    __shared__ float As[16 * 132];   // [k][row]
    __shared__ float Bs[16 * 132];   // [k][col]
    const int t = threadIdx.x, tx = t & 15, ty = t >> 4;
    const int row0 = blockIdx.y * 128, col0 = blockIdx.x * 128;

    float acc[8][8] = {};

    for (int k0 = 0; k0 < K; k0 += 16) {
        {   // A: 128 rows x 16 k
            int row = t >> 1, kq = (t & 1) * 4;
#pragma unroll
            for (int g = 0; g < 2; g++) {
                int kk = kq + g * 8;
                float4 a = *(const float4*)&A[(size_t)(row0 + row) * lda + k0 + kk];
                As[(kk + 0) * 132 + row] = a.x; As[(kk + 1) * 132 + row] = a.y;
                As[(kk + 2) * 132 + row] = a.z; As[(kk + 3) * 132 + row] = a.w;
            }
        }
        if (!TRANSB) {
            int kk = t >> 5, c4 = (t & 31) * 4;
#pragma unroll
            for (int g = 0; g < 2; g++) {
                int k2 = kk + g * 8;
                float4 b = *(const float4*)&B[(size_t)(k0 + k2) * ldb + col0 + c4];
                *(float4*)&Bs[k2 * 132 + c4] = b;
            }
        } else {
            int n = t >> 1, kq = (t & 1) * 4;
#pragma unroll
            for (int g = 0; g < 2; g++) {
                int kk = kq + g * 8;
                float4 b = *(const float4*)&B[(size_t)(col0 + n) * ldb + k0 + kk];
                Bs[(kk + 0) * 132 + n] = b.x; Bs[(kk + 1) * 132 + n] = b.y;
                Bs[(kk + 2) * 132 + n] = b.z; Bs[(kk + 3) * 132 + n] = b.w;
            }
        }
        __syncthreads();
#pragma unroll
        for (int k = 0; k < 16; k++) {
            float4 a0 = *(const float4*)&As[k * 132 + ty * 8];
            float4 a1 = *(const float4*)&As[k * 132 + ty * 8 + 4];
            float4 b0 = *(const float4*)&Bs[k * 132 + tx * 8];
            float4 b1 = *(const float4*)&Bs[k * 132 + tx * 8 + 4];
            float av[8] = {a0.x, a0.y, a0.z, a0.w, a1.x, a1.y, a1.z, a1.w};
            float bv[8] = {b0.x, b0.y, b0.z, b0.w, b1.x, b1.y, b1.z, b1.w};
#pragma unroll
            for (int i = 0; i < 8; i++)
#pragma unroll
                for (int j = 0; j < 8; j++) acc[i][j] += av[i] * bv[j];
        }
        __syncthreads();
    }
#pragma unroll
    for (int i = 0; i < 8; i++) {
        int r = row0 + ty * 8 + i;
#pragma unroll
        for (int j = 0; j < 8; j++) {
            int c = col0 + tx * 8 + j;
            float v = alpha * acc[i][j];
            if (ACT == 3) {
                v = (r == c) ? -1e9f : fmaxf(v, 0.f);
            } else {
                if (bias) v += bias[c];
                if (ACT == 1) v = fmaxf(v, 0.f);
            }
            C[(size_t)r * ldc + c] = v;
        }
    }
}

// ---------------- top-k selection over precomputed sim rows ----------------
__global__ void __launch_bounds__(128)
select_kernel(const float* __restrict__ sim, int* __restrict__ nbr)
{
    __shared__ float s[NNODE];
    __shared__ float wv[4];
    __shared__ int   wi[4];
    const int row = blockIdx.x, t = threadIdx.x;

    const float4* src = (const float4*)(sim + (size_t)row * NNODE);
    for (int i = t; i < NNODE / 4; i += 128) *(float4*)&s[i * 4] = src[i];
    __syncthreads();

    for (int it = 0; it < TOPK; it++) {
        float bv = -1e30f; int bi = NNODE;
        for (int j = t; j < NNODE; j += 128) {
            float v = s[j];
            if (v > bv || (v == bv && j < bi)) { bv = v; bi = j; }
        }
#pragma unroll
        for (int off = 16; off >= 1; off >>= 1) {
            float v2 = __shfl_down_sync(0xffffffffu, bv, off);
            int   i2 = __shfl_down_sync(0xffffffffu, bi, off);
            if (v2 > bv || (v2 == bv && i2 < bi)) { bv = v2; bi = i2; }
        }
        if ((t & 31) == 0) { wv[t >> 5] = bv; wi[t >> 5] = bi; }
        __syncthreads();
        if (t == 0) {
#pragma unroll
            for (int w = 1; w < 4; w++)
                if (wv[w] > bv || (wv[w] == bv && wi[w] < bi)) { bv = wv[w]; bi = wi[w]; }
            nbr[row * NEDGE + it] = bi;
            s[bi] = -2e9f;
        }
        __syncthreads();
    }
    if (t == 0) nbr[row * NEDGE + TOPK] = row;
}

// ---------------- fused flash attention (transposed smem tiles) ----------------
// Grid: (qtile 0..63, head 0..3). Q pre-scaled by 1/8. dh=64.
#define FST 68
#define FA_SMEM_FLOATS (4 * 64 * FST + 3 * 64)
__global__ void __launch_bounds__(256)
flash_attn(const float* __restrict__ qkv, float* __restrict__ out)
{
    extern __shared__ float sm[];
    float* Qs   = sm;                 // [d][q]
    float* Ks   = Qs + 64 * FST;      // [d][k]
    float* Vs   = Ks + 64 * FST;      // [k][c]
    float* Ps   = Vs + 64 * FST;      // [k][q]
    float* m_s  = Ps + 64 * FST;
    float* l_s  = m_s + 64;
    float* sc_s = l_s + 64;

    const int h  = blockIdx.y;
    const int q0 = blockIdx.x * 64;
    const int t  = threadIdx.x;
    const int tx = t & 15, ty = t >> 4;

    for (int i = t; i < 64 * 64; i += 256) {
        int r = i >> 6, c = i & 63;
        Qs[c * FST + r] = qkv[(size_t)(q0 + r) * 768 + h * 64 + c] * 0.125f;
    }
    if (t < 64) { m_s[t] = -1e30f; l_s[t] = 0.f; }

    float o[4][4] = {};

    for (int k0 = 0; k0 < NNODE; k0 += 64) {
        __syncthreads();
        for (int i = t; i < 64 * 64; i += 256) {
            int r = i >> 6, c = i & 63;
            Ks[c * FST + r] = qkv[(size_t)(k0 + r) * 768 + 256 + h * 64 + c];
            Vs[r * FST + c] = qkv[(size_t)(k0 + r) * 768 + 512 + h * 64 + c];
        }
        __syncthreads();

        float s[4][4] = {};
#pragma unroll
        for (int d = 0; d < 64; d++) {
            float4 a = *(const float4*)&Qs[d * FST + ty * 4];
            float4 b = *(const float4*)&Ks[d * FST + tx * 4];
            s[0][0] += a.x * b.x; s[0][1] += a.x * b.y; s[0][2] += a.x * b.z; s[0][3] += a.x * b.w;
            s[1][0] += a.y * b.x; s[1][1] += a.y * b.y; s[1][2] += a.y * b.z; s[1][3] += a.y * b.w;
            s[2][0] += a.z * b.x; s[2][1] += a.z * b.y; s[2][2] += a.z * b.z; s[2][3] += a.z * b.w;
            s[3][0] += a.w * b.x; s[3][1] += a.w * b.y; s[3][2] += a.w * b.z; s[3][3] += a.w * b.w;
        }
#pragma unroll
        for (int j = 0; j < 4; j++) {
            float4 v = make_float4(s[0][j], s[1][j], s[2][j], s[3][j]);
            *(float4*)&Ps[(tx * 4 + j) * FST + ty * 4] = v;
        }
        __syncthreads();

        if (t < 64) {
            float m_old = m_s[t], mt = m_old;
#pragma unroll 8
            for (int c = 0; c < 64; c++) mt = fmaxf(mt, Ps[c * FST + t]);
            float sc = __expf(m_old - mt);
            float l = l_s[t] * sc;
#pragma unroll 8
            for (int c = 0; c < 64; c++) {
                float p = __expf(Ps[c * FST + t] - mt);
                Ps[c * FST + t] = p;
                l += p;
            }
            m_s[t] = mt; l_s[t] = l; sc_s[t] = sc;
        }
        __syncthreads();

        float scl0 = sc_s[ty * 4 + 0], scl1 = sc_s[ty * 4 + 1];
        float scl2 = sc_s[ty * 4 + 2], scl3 = sc_s[ty * 4 + 3];
#pragma unroll
        for (int j = 0; j < 4; j++) {
            o[0][j] *= scl0; o[1][j] *= scl1; o[2][j] *= scl2; o[3][j] *= scl3;
        }
#pragma unroll
        for (int k = 0; k < 64; k++) {
            float4 p = *(const float4*)&Ps[k * FST + ty * 4];
            float4 v = *(const float4*)&Vs[k * FST + tx * 4];
            o[0][0] += p.x * v.x; o[0][1] += p.x * v.y; o[0][2] += p.x * v.z; o[0][3] += p.x * v.w;
            o[1][0] += p.y * v.x; o[1][1] += p.y * v.y; o[1][2] += p.y * v.z; o[1][3] += p.y * v.w;
            o[2][0] += p.z * v.x; o[2][1] += p.z * v.y; o[2][2] += p.z * v.z; o[2][3] += p.z * v.w;
            o[3][0] += p.w * v.x; o[3][1] += p.w * v.y; o[3][2] += p.w * v.z; o[3][3] += p.w * v.w;
        }
    }
    __syncthreads();

#pragma unroll
    for (int i = 0; i < 4; i++) {
        float inv = 1.f / l_s[ty * 4 + i];
#pragma unroll
        for (int j = 0; j < 4; j++)
            out[(size_t)(q0 + ty * 4 + i) * DIM + h * 64 + tx * 4 + j] = o[i][j] * inv;
    }
}

// ---------------- GAT per-node attention scores ----------------
__global__ void __launch_bounds__(256)
gat_score(const float* __restrict__ hf, const float* __restrict__ asrc,
          const float* __restrict__ adst, float* __restrict__ ssrc,
          float* __restrict__ sdst, int heads)
{
    const int n = blockIdx.x, t = threadIdx.x;
    const int F = DIM / heads;
    __shared__ float rs[256], rd[256];
    float v = hf[(size_t)n * DIM + t];
    rs[t] = v * asrc[t];
    rd[t] = v * adst[t];
    __syncthreads();
    for (int off = F >> 1; off >= 1; off >>= 1) {
        if ((t & (F - 1)) < off) { rs[t] += rs[t + off]; rd[t] += rd[t + off]; }
        __syncthreads();
    }
    if ((t & (F - 1)) == 0) {
        int hh = t / F;
        ssrc[n * heads + hh] = rs[t];
        sdst[n * heads + hh] = rd[t];
    }
}

// ---------------- GAT aggregation (17 fixed edges per dst) ----------------
__global__ void __launch_bounds__(256)
gat_agg(const float* __restrict__ hf, const int* __restrict__ nbr,
        const float* __restrict__ ssrc, const float* __restrict__ sdst,
        const float* __restrict__ bias, float* __restrict__ out,
        int heads, int relu, int transout)
{
    const int n = blockIdx.x, t = threadIdx.x;
    const int F = DIM / heads;
    const int hh = t / F, f = t - hh * F;
    __shared__ int   nb[NEDGE];
    __shared__ float al[4 * NEDGE];

    if (t < NEDGE) nb[t] = nbr[n * NEDGE + t];
    __syncthreads();
    if (f < NEDGE) {
        float e = ssrc[nb[f] * heads + hh] + sdst[n * heads + hh];
        e = (e > 0.f) ? e : 0.2f * e;
        al[hh * NEDGE + f] = e;
    }
    __syncthreads();
    if (f == 0) {
        float m = -1e30f;
        for (int j = 0; j < NEDGE; j++) m = fmaxf(m, al[hh * NEDGE + j]);
        float s = 0.f;
        for (int j = 0; j < NEDGE; j++) { float p = expf(al[hh * NEDGE + j] - m); al[hh * NEDGE + j] = p; s += p; }
        float inv = 1.f / s;
        for (int j = 0; j < NEDGE; j++) al[hh * NEDGE + j] *= inv;
    }
    __syncthreads();
    float acc = 0.f;
#pragma unroll
    for (int j = 0; j < NEDGE; j++)
        acc += al[hh * NEDGE + j] * hf[(size_t)nb[j] * DIM + t];
    float v = acc + bias[t];
    if (relu) v = fmaxf(v, 0.f);
    if (transout) out[(size_t)t * NNODE + n] = v;
    else          out[(size_t)n * DIM + t] = v;
}

// ---------------- layernorm (in place, 256-dim rows) ----------------
__global__ void __launch_bounds__(256)
ln_kernel(float* __restrict__ x, const float* __restrict__ g, const float* __restrict__ b)
{
    const int n = blockIdx.x, t = threadIdx.x;
    __shared__ float red[256];
    float v = x[(size_t)n * DIM + t];
    red[t] = v; __syncthreads();
    for (int off = 128; off >= 1; off >>= 1) { if (t < off) red[t] += red[t + off]; __syncthreads(); }
    float mu = red[0] * (1.f / 256.f); __syncthreads();
    float d = v - mu;
    red[t] = d * d; __syncthreads();
    for (int off = 128; off >= 1; off >>= 1) { if (t < off) red[t] += red[t + off]; __syncthreads(); }
    float var = red[0] * (1.f / 256.f);
    x[(size_t)n * DIM + t] = d * rsqrtf(var + 1e-5f) * g[t] + b[t];
}

// ---------------- host orchestration ----------------
extern "C" void kernel_launch(void* const* d_in, const int* in_sizes, int n_in,
                              void* d_out, int out_size)
{
    const float* window   = (const float*)d_in[0];
    const float* gl_w     = (const float*)d_in[1];
    const float* gl_b     = (const float*)d_in[2];
    const float* enc_W    = (const float*)d_in[3];
    const float* enc_asrc = (const float*)d_in[4];
    const float* enc_adst = (const float*)d_in[5];
    const float* enc_b    = (const float*)d_in[6];
    const float* tr_wqkv  = (const float*)d_in[7];
    const float* tr_bqkv  = (const float*)d_in[8];
    const float* tr_wo    = (const float*)d_in[9];
    const float* tr_bo    = (const float*)d_in[10];
    const float* ln1g     = (const float*)d_in[11];
    const float* ln1b     = (const float*)d_in[12];
    const float* w1       = (const float*)d_in[13];
    const float* b1       = (const float*)d_in[14];
    const float* w2       = (const float*)d_in[15];
    const float* b2       = (const float*)d_in[16];
    const float* ln2g     = (const float*)d_in[17];
    const float* ln2b     = (const float*)d_in[18];
    const float* skw      = (const float*)d_in[19];
    const float* skb      = (const float*)d_in[20];
    const float* dec_W    = (const float*)d_in[21];
    const float* dec_asrc = (const float*)d_in[22];
    const float* dec_adst = (const float*)d_in[23];
    const float* dec_b    = (const float*)d_in[24];
    const float* dlW      = (const float*)d_in[25];
    const float* dlas     = (const float*)d_in[26];
    const float* dlad     = (const float*)d_in[27];
    const float* dlb      = (const float*)d_in[28];

    float *h, *x, *hf, *qkv, *attn, *tmp, *ff, *sim, *ssrc, *sdst;
    int* nbr;
    cudaGetSymbolAddress((void**)&h,    g_h);
    cudaGetSymbolAddress((void**)&x,    g_x);
    cudaGetSymbolAddress((void**)&hf,   g_hf);
    cudaGetSymbolAddress((void**)&qkv,  g_qkv);
    cudaGetSymbolAddress((void**)&attn, g_attn);
    cudaGetSymbolAddress((void**)&tmp,  g_tmp);
    cudaGetSymbolAddress((void**)&ff,   g_ff);
    cudaGetSymbolAddress((void**)&sim,  g_sim);
    cudaGetSymbolAddress((void**)&ssrc, g_ssrc);
    cudaGetSymbolAddress((void**)&sdst, g_sdst);
    cudaGetSymbolAddress((void**)&nbr,  g_nbr);

    cudaFuncSetAttribute(flash_attn, cudaFuncAttributeMaxDynamicSharedMemorySize,
                         FA_SMEM_FLOATS * (int)sizeof(float));

    // 1. graph learning: h = tanh(window @ gl_w + gl_b); sim = relu(h@h^T), diag -1e9; top-16
    sgemm2<0, 2, 0><<<dim3(4, 64), 256>>>(window, gl_w, h, gl_b, nullptr,
                                          4096, 256, 256, 256, 256, 256, 1.f);
    sgemm_big<1, 3><<<dim3(32, 32), 256>>>(h, h, sim, nullptr,
                                           4096, 4096, 256, 256, 256, 4096, 1.f);
    select_kernel<<<NNODE, 128>>>(sim, nbr);

    // 2. encoder: 3 GAT layers (4 heads) with ReLU
    const float* xin = window;
    for (int i = 0; i < 3; i++) {
        sgemm2<0, 0, 0><<<dim3(4, 64), 256>>>(xin, enc_W + (size_t)i * 65536, hf, nullptr, nullptr,
                                              4096, 256, 256, 256, 256, 256, 1.f);
        gat_score<<<NNODE, 256>>>(hf, enc_asrc + i * 256, enc_adst + i * 256, ssrc, sdst, 4);
        gat_agg<<<NNODE, 256>>>(hf, nbr, ssrc, sdst, enc_b + i * 256, x, 4, 1, 0);
        xin = x;
    }

    // 3. transformer bottleneck x2 (4 heads, dh=64)
    for (int l = 0; l < 2; l++) {
        sgemm_big<1, 0><<<dim3(6, 32), 256>>>(x, tr_wqkv + (size_t)l * 768 * 256, qkv,
                                              tr_bqkv + l * 768,
                                              4096, 768, 256, 256, 256, 768, 1.f);
        flash_attn<<<dim3(64, 4), 256, FA_SMEM_FLOATS * sizeof(float)>>>(qkv, attn);
        // x = x + attn @ wo^T + bo   (fused residual, in-place)
        sgemm2<1, 0, 1><<<dim3(4, 64), 256>>>(attn, tr_wo + (size_t)l * 65536, x,
                                              tr_bo + l * 256, x,
                                              4096, 256, 256, 256, 256, 256, 1.f);
        ln_kernel<<<NNODE, 256>>>(x, ln1g + l * 256, ln1b + l * 256);
        sgemm_big<0, 1><<<dim3(4, 32), 256>>>(x, w1 + (size_t)l * 131072, ff, b1 + l * 512,
                                              4096, 512, 256, 256, 512, 512, 1.f);
        // x = x + ff @ w2 + b2   (fused residual, in-place)
        sgemm2<0, 0, 1><<<dim3(4, 64), 256>>>(ff, w2 + (size_t)l * 131072, x, b2 + l * 256, x,
                                              4096, 256, 512, 512, 256, 256, 1.f);
        ln_kernel<<<NNODE, 256>>>(x, ln2g + l * 256, ln2b + l * 256);
    }

    // 4. skip connection: x = x + window @ skip_w + skip_b   (fused)
    sgemm2<0, 0, 1><<<dim3(4, 64), 256>>>(window, skw, x, skb, x,
                                          4096, 256, 256, 256, 256, 256, 1.f);

    // 5. decoder: 2 GAT layers (4 heads) with ReLU
    for (int i = 0; i < 2; i++) {
        sgemm2<0, 0, 0><<<dim3(4, 64), 256>>>(x, dec_W + (size_t)i * 65536, hf, nullptr, nullptr,
                                              4096, 256, 256, 256, 256, 256, 1.f);
        gat_score<<<NNODE, 256>>>(hf, dec_asrc + i * 256, dec_adst + i * 256, ssrc, sdst, 4);
        gat_agg<<<NNODE, 256>>>(hf, nbr, ssrc, sdst, dec_b + i * 256, x, 4, 1, 0);
    }

    // 6. final single-head GAT, output transposed [256, 4096]
    sgemm2<0, 0, 0><<<dim3(4, 64), 256>>>(x, dlW, hf, nullptr, nullptr,
                                          4096, 256, 256, 256, 256, 256, 1.f);
    gat_score<<<NNODE, 256>>>(hf, dlas, dlad, ssrc, sdst, 1);
    gat_agg<<<NNODE, 256>>>(hf, nbr, ssrc, sdst, dlb, (float*)d_out, 1, 0, 1);
}